// round 10
// baseline (speedup 1.0000x reference)
#include <cuda_runtime.h>

#define NCTA   128
#define TPB    256
#define PP     1024
#define DD     32
#define RS     1032
#define RT     16
#define MAXIT  30
#define EPSV   0.1f
#define LN2F   0.69314718055994530942f
#define ALPHA  14.4269504088896340736f   /* 1/(eps*ln2) */
#define THRESH 0.1f

typedef unsigned long long u64;

__device__ unsigned          g_cnt[4 * 32];   // 4 barriers, padded counters
__device__ volatile unsigned g_gen[4 * 32];   // 4 barriers, padded gen flags
__device__ float    g_ps[4 * 64 * PP];        // plain-sum partials [batch][sub][col]
__device__ float2   g_pm[4 * 64 * PP];        // (max,sum) partials, iter 0
__device__ float    g_b2[4 * PP];             // B per (batch, col)
__device__ float    g_errpart[2 * NCTA];      // per-phase per-CTA err
__device__ double   g_costp[2 * NCTA];        // per-phase per-CTA cost partial

struct Smem {
    float  K2[2][RT * RS];     // 2 x 66 KB
    float  bb[2][PP];          // B vectors (local copies)
    float  lnu2[2][PP];
    float  ystage[256 * DD];   // setup staging
    double redd[TPB];
    float  cmbS[16][17];
    float2 cmbM[16][17];
    float  A2s[2][RT];
    float  lmu2s[2][RT];
    float  rowShift[2][RT];
    float  errw[2][8];
    float  errTot;
    float  Sx, Sy;
};

__device__ __forceinline__ float ex2f(float x){ float r; asm("ex2.approx.ftz.f32 %0, %1;" : "=f"(r) : "f"(x)); return r; }
__device__ __forceinline__ float lg2f(float x){ float r; asm("lg2.approx.f32 %0, %1;" : "=f"(r) : "f"(x)); return r; }
__device__ __forceinline__ u64 pk2(float lo, float hi){ u64 r; asm("mov.b64 %0, {%1, %2};" : "=l"(r) : "f"(lo), "f"(hi)); return r; }
__device__ __forceinline__ void upk2(u64 v, float& lo, float& hi){ asm("mov.b64 {%0, %1}, %2;" : "=f"(lo), "=f"(hi) : "l"(v)); }
__device__ __forceinline__ void fma2(u64& d, u64 a, u64 b){ asm("fma.rn.f32x2 %0, %1, %2, %0;" : "+l"(d) : "l"(a), "l"(b)); }
__device__ __forceinline__ u64 add2(u64 a, u64 b){ u64 r; asm("add.rn.f32x2 %0, %1, %2;" : "=l"(r) : "l"(a), "l"(b)); return r; }

// split arrive / wait (R3-style counter + gen, per barrier slot k)
__device__ __forceinline__ void barArrive(int k, unsigned target) {
    __syncthreads();
    if (threadIdx.x == 0) {
        __threadfence();
        if (atomicAdd(&g_cnt[k * 32], 1u) == NCTA - 1u) {
            g_cnt[k * 32] = 0;
            __threadfence();
            g_gen[k * 32] = target;
        }
    }
}
__device__ __forceinline__ void barWait(int k, unsigned target) {
    if (threadIdx.x == 0) {
        while (g_gen[k * 32] != target) { }
        __threadfence();
    }
    __syncthreads();
}

__global__ void __launch_bounds__(TPB, 1)
sinkhorn_kernel(const float* __restrict__ gx, const float* __restrict__ gy,
                const float* __restrict__ gxw, const float* __restrict__ gyw,
                float* __restrict__ gout)
{
    extern __shared__ __align__(16) char smraw[];
    Smem* S = reinterpret_cast<Smem*>(smraw);

    const int tid  = threadIdx.x;
    const int lane = tid & 31;
    const int warp = tid >> 5;       // 0..7
    const int bid  = blockIdx.x;
    const int pair = bid >> 6;       // 0: batches 0,1   1: batches 2,3
    const int sub  = bid & 63;       // 0..63
    const int r0   = sub * RT;       // first row of both tiles

    unsigned bse[4];
#pragma unroll
    for (int k = 0; k < 4; k++) bse[k] = g_gen[k * 32];

    // ---- global weight sums (redundant per CTA, deterministic) ----
    {
        float px = 0.f, py = 0.f;
        for (int k = tid; k < 4096; k += TPB) { px += gxw[k]; py += gyw[k]; }
        S->redd[tid] = (double)px; __syncthreads();
        for (int s = TPB/2; s > 0; s >>= 1) { if (tid < s) S->redd[tid] += S->redd[tid+s]; __syncthreads(); }
        if (tid == 0) S->Sx = (float)S->redd[0];
        __syncthreads();
        S->redd[tid] = (double)py; __syncthreads();
        for (int s = TPB/2; s > 0; s >>= 1) { if (tid < s) S->redd[tid] += S->redd[tid+s]; __syncthreads(); }
        if (tid == 0) S->Sy = (float)S->redd[0];
        __syncthreads();
    }

    if (tid < 32) {
        const int m = tid >> 4, r = tid & 15;
        S->lmu2s[m][r] = lg2f(gxw[(pair*2+m) * PP + r0 + r] / S->Sx + 1e-8f);
        S->A2s[m][r]   = 0.f;
    }
    for (int c = tid; c < PP; c += TPB) {
        S->lnu2[0][c] = lg2f(gyw[(pair*2+0) * PP + c] / S->Sy + 1e-8f);
        S->lnu2[1][c] = lg2f(gyw[(pair*2+1) * PP + c] / S->Sy + 1e-8f);
    }

    // ---- build K2 tiles for both batches ----
    for (int m = 0; m < 2; m++) {
        const int batch = pair * 2 + m;
        const float* ybase = gy + (size_t)batch * PP * DD;
        // temp: ALPHA*|y|^2 into bb[m]
        for (int c = tid; c < PP; c += TPB) {
            const float4* yc = (const float4*)(ybase + c * DD);
            float s = 0.f;
#pragma unroll
            for (int q = 0; q < 8; q++) { float4 v = yc[q]; s += v.x*v.x + v.y*v.y + v.z*v.z + v.w*v.w; }
            S->bb[m][c] = s * ALPHA;
        }
        const int row = lane & 15;
        float xv[32];
        {
            const float4* xr = (const float4*)(gx + (size_t)(batch * PP + r0 + row) * DD);
#pragma unroll
            for (int q = 0; q < 8; q++) {
                float4 v = xr[q];
                xv[4*q] = v.x; xv[4*q+1] = v.y; xv[4*q+2] = v.z; xv[4*q+3] = v.w;
            }
        }
        float x2 = 0.f;
#pragma unroll
        for (int d = 0; d < 32; d++) x2 += xv[d] * xv[d];
        const float cx = ALPHA * x2;
        u64 xp[16];
#pragma unroll
        for (int q = 0; q < 16; q++) xp[q] = pk2(xv[2*q], xv[2*q+1]);
        __syncthreads();

        for (int chunk = 0; chunk < 4; chunk++) {
            const int j0 = chunk * 256;
            const float4* ysrc = (const float4*)(ybase + j0 * DD);
            float4* yst = (float4*)S->ystage;
#pragma unroll
            for (int q = 0; q < 8; q++) yst[tid + 256 * q] = ysrc[tid + 256 * q];
            __syncthreads();
#pragma unroll 4
            for (int step = 0; step < 16; step++) {
                const int jl = step * 16 + warp * 2 + (lane >> 4);
                const ulonglong2* yp = (const ulonglong2*)(S->ystage + jl * DD);
                u64 acc[4] = {0ull, 0ull, 0ull, 0ull};
#pragma unroll
                for (int q = 0; q < 8; q++) {
                    ulonglong2 w = yp[q];
                    fma2(acc[(2*q)   & 3], xp[2*q],     w.x);
                    fma2(acc[(2*q+1) & 3], xp[2*q + 1], w.y);
                }
                u64 st = add2(add2(acc[0], acc[1]), add2(acc[2], acc[3]));
                float lo, hi; upk2(st, lo, hi);
                float dot = lo + hi;
                S->K2[m][row * RS + j0 + jl] = fmaf(dot, 2.f * ALPHA, -(cx + S->bb[m][j0 + jl]));
            }
            __syncthreads();
        }
    }

    // row maxes for iter-0 shifts (B=0 -> exact); warp w: batch w&1, rows (w>>1)*4..+3
    {
        const int m = warp & 1, rb = (warp >> 1) * 4;
#pragma unroll
        for (int k = 0; k < 4; k++) {
            const int r = rb + k;
            const float4* kr = (const float4*)(S->K2[m] + r * RS);
            float mx = -1e30f;
#pragma unroll
            for (int q = 0; q < 8; q++) {
                float4 a = kr[lane + 32 * q];
                mx = fmaxf(mx, fmaxf(fmaxf(a.x, a.y), fmaxf(a.z, a.w)));
            }
#pragma unroll
            for (int o = 16; o; o >>= 1) mx = fmaxf(mx, __shfl_xor_sync(0xffffffffu, mx, o));
            if (lane == 0) S->rowShift[m][r] = mx;
        }
    }
#pragma unroll
    for (int cc = 0; cc < 4; cc++) { S->bb[0][tid + 256*cc] = 0.f; S->bb[1][tid + 256*cc] = 0.f; }
    __syncthreads();

    const int c0 = 2 * tid, c1 = 2 * tid + 1, c2 = 2 * tid + 512, c3 = 2 * tid + 513;
    const int colL = tid & 15, grp = tid >> 4;

    // ================= pipelined Sinkhorn iterations =================
    int iter = 0;
    for (;;) {
        const unsigned t1 = bse[0] + (unsigned)iter + 1u;
        const unsigned t2 = bse[1] + (unsigned)iter + 1u;
        const unsigned t3 = bse[2] + (unsigned)iter + 1u;
        const unsigned t4 = bse[3] + (unsigned)iter + 1u;

        // ---- phase m: row update + column partials + arrive ----
        for (int m = 0; m < 2; m++) {
            const int batch = pair * 2 + m;
            // row update: warp handles rows 2w, 2w+1
            {
                const float4* b4  = (const float4*)S->bb[m];
                const float4* kr0 = (const float4*)(S->K2[m] + (warp * 2 + 0) * RS);
                const float4* kr1 = (const float4*)(S->K2[m] + (warp * 2 + 1) * RS);
                const float m0 = S->rowShift[m][warp * 2 + 0];
                const float m1 = S->rowShift[m][warp * 2 + 1];
                float s0 = 0.f, s1 = 0.f;
#pragma unroll
                for (int q = 0; q < 8; q++) {
                    const int ix = lane + 32 * q;
                    float4 b = b4[ix];
                    float4 a0 = kr0[ix], a1 = kr1[ix];
                    s0 += ex2f(a0.x + b.x - m0) + ex2f(a0.y + b.y - m0)
                        + ex2f(a0.z + b.z - m0) + ex2f(a0.w + b.w - m0);
                    s1 += ex2f(a1.x + b.x - m1) + ex2f(a1.y + b.y - m1)
                        + ex2f(a1.z + b.z - m1) + ex2f(a1.w + b.w - m1);
                }
#pragma unroll
                for (int o = 16; o; o >>= 1) {
                    s0 += __shfl_xor_sync(0xffffffffu, s0, o);
                    s1 += __shfl_xor_sync(0xffffffffu, s1, o);
                }
                if (lane == 0) {
                    float lse0 = m0 + lg2f(s0), lse1 = m1 + lg2f(s1);
                    const int r = warp * 2;
                    float a0 = S->lmu2s[m][r+0] - lse0, a1 = S->lmu2s[m][r+1] - lse1;
                    S->errw[m][warp] = fabsf(a0 - S->A2s[m][r+0]) + fabsf(a1 - S->A2s[m][r+1]);
                    S->A2s[m][r+0] = a0; S->A2s[m][r+1] = a1;
                    S->rowShift[m][r+0] = lse0; S->rowShift[m][r+1] = lse1;
                }
            }
            __syncthreads();
            if (tid == 0) {
                float e = ((S->errw[m][0] + S->errw[m][1]) + (S->errw[m][2] + S->errw[m][3]))
                        + ((S->errw[m][4] + S->errw[m][5]) + (S->errw[m][6] + S->errw[m][7]));
                __stcg(&g_errpart[m * NCTA + bid], e);
            }

            // column partials over own 16 rows
            if (iter == 0) {
                float m0=-1e30f, m1=-1e30f, m2=-1e30f, m3=-1e30f;
#pragma unroll
                for (int r = 0; r < RT; r++) {
                    const float ar = S->A2s[m][r];
                    const float* kr = S->K2[m] + r * RS;
                    float2 ka = *(const float2*)(kr + c0);
                    float2 kb = *(const float2*)(kr + c2);
                    m0 = fmaxf(m0, ka.x + ar); m1 = fmaxf(m1, ka.y + ar);
                    m2 = fmaxf(m2, kb.x + ar); m3 = fmaxf(m3, kb.y + ar);
                }
                float s0=0.f, s1=0.f, s2=0.f, s3=0.f;
#pragma unroll
                for (int r = 0; r < RT; r++) {
                    const float ar = S->A2s[m][r];
                    const float* kr = S->K2[m] + r * RS;
                    float2 ka = *(const float2*)(kr + c0);
                    float2 kb = *(const float2*)(kr + c2);
                    s0 += ex2f(ka.x + (ar - m0)); s1 += ex2f(ka.y + (ar - m1));
                    s2 += ex2f(kb.x + (ar - m2)); s3 += ex2f(kb.y + (ar - m3));
                }
                float2* pm = g_pm + (size_t)(batch * 64 + sub) * PP;
                *(float4*)(pm + c0) = make_float4(m0, s0, m1, s1);
                *(float4*)(pm + c2) = make_float4(m2, s2, m3, s3);
            } else {
                const float mc0 = S->lnu2[m][c0] - S->bb[m][c0];
                const float mc1 = S->lnu2[m][c1] - S->bb[m][c1];
                const float mc2 = S->lnu2[m][c2] - S->bb[m][c2];
                const float mc3 = S->lnu2[m][c3] - S->bb[m][c3];
                float s0 = 0.f, s1 = 0.f, s2 = 0.f, s3 = 0.f;
#pragma unroll
                for (int r = 0; r < RT; r++) {
                    const float ar = S->A2s[m][r];
                    const float* kr = S->K2[m] + r * RS;
                    float2 ka = *(const float2*)(kr + c0);
                    float2 kb = *(const float2*)(kr + c2);
                    s0 += ex2f(ka.x + (ar - mc0)); s1 += ex2f(ka.y + (ar - mc1));
                    s2 += ex2f(kb.x + (ar - mc2)); s3 += ex2f(kb.y + (ar - mc3));
                }
                float* ps = g_ps + (size_t)(batch * 64 + sub) * PP;
                *(float2*)(ps + c0) = make_float2(s0, s1);
                *(float2*)(ps + c2) = make_float2(s2, s3);
            }
            barArrive(m, m == 0 ? t1 : t2);   // XP / XQ
        }

        // ---- combines (waits overlapped by the other phase's compute) ----
        for (int m = 0; m < 2; m++) {
            const int batch = pair * 2 + m;
            barWait(m, m == 0 ? t1 : t2);
            const int c = sub * RT + colL;
            if (iter == 0) {
                const float2* base = g_pm + (size_t)(batch * 64) * PP + c;
                float2 p = __ldcg(base + (grp * 4 + 0) * PP);
#pragma unroll
                for (int k = 1; k < 4; k++) {
                    float2 q = __ldcg(base + (grp * 4 + k) * PP);
                    float mn = fmaxf(p.x, q.x);
                    p.y = p.y * ex2f(p.x - mn) + q.y * ex2f(q.x - mn);
                    p.x = mn;
                }
                S->cmbM[grp][colL] = p;
                __syncthreads();
                if (tid < 16) {
                    float2 p2 = S->cmbM[0][tid];
#pragma unroll
                    for (int g = 1; g < 16; g++) {
                        float2 q = S->cmbM[g][tid];
                        float mn = fmaxf(p2.x, q.x);
                        p2.y = p2.y * ex2f(p2.x - mn) + q.y * ex2f(q.x - mn);
                        p2.x = mn;
                    }
                    const int cc = sub * RT + tid;
                    float lse = p2.x + lg2f(p2.y);
                    __stcg(&g_b2[batch * PP + cc], S->lnu2[m][cc] - lse);
                }
            } else {
                const float* base = g_ps + (size_t)(batch * 64) * PP + c;
                float s = __ldcg(base + (grp * 4 + 0) * PP) + __ldcg(base + (grp * 4 + 1) * PP)
                        + __ldcg(base + (grp * 4 + 2) * PP) + __ldcg(base + (grp * 4 + 3) * PP);
                S->cmbS[grp][colL] = s;
                __syncthreads();
                if (tid < 16) {
                    float tot = 0.f;
#pragma unroll
                    for (int g = 0; g < 16; g++) tot += S->cmbS[g][tid];
                    const int cc = sub * RT + tid;
                    float shift = S->lnu2[m][cc] - S->bb[m][cc];
                    float lse = shift + lg2f(tot);
                    __stcg(&g_b2[batch * PP + cc], S->lnu2[m][cc] - lse);
                }
            }
            barArrive(2 + m, m == 0 ? t3 : t4);   // YP / YQ
        }

        // ---- reloads + err decision ----
        barWait(2, t3);
        ((float4*)S->bb[0])[tid] = __ldcg(((const float4*)(g_b2 + (pair*2+0) * PP)) + tid);
        barWait(3, t4);
        ((float4*)S->bb[1])[tid] = __ldcg(((const float4*)(g_b2 + (pair*2+1) * PP)) + tid);
        if (warp == 0) {
            float e = 0.f;
#pragma unroll
            for (int k = 0; k < 8; k++) e += __ldcg(&g_errpart[lane + 32 * k]);
#pragma unroll
            for (int o = 16; o; o >>= 1) e += __shfl_xor_sync(0xffffffffu, e, o);
            if (lane == 0) S->errTot = e;
        }
        __syncthreads();

        iter++;
        if (iter >= MAXIT) break;
        if (S->errTot * (EPSV * LN2F * 0.25f) < THRESH) break;
    }

    // ---- final cost per phase ----
    for (int m = 0; m < 2; m++) {
        const float bc0 = S->bb[m][c0], bc1 = S->bb[m][c1];
        const float bc2 = S->bb[m][c2], bc3 = S->bb[m][c3];
        float acc = 0.f;
#pragma unroll
        for (int r = 0; r < RT; r++) {
            const float ar = S->A2s[m][r];
            const float* kr = S->K2[m] + r * RS;
            float2 ka = *(const float2*)(kr + c0);
            float2 kb = *(const float2*)(kr + c2);
            acc = fmaf(ex2f(ka.x + ar + bc0), ka.x, acc);
            acc = fmaf(ex2f(ka.y + ar + bc1), ka.y, acc);
            acc = fmaf(ex2f(kb.x + ar + bc2), kb.x, acc);
            acc = fmaf(ex2f(kb.y + ar + bc3), kb.y, acc);
        }
        S->redd[tid] = (double)acc; __syncthreads();
        for (int s = TPB/2; s > 0; s >>= 1) { if (tid < s) S->redd[tid] += S->redd[tid+s]; __syncthreads(); }
        if (tid == 0) __stcg(&g_costp[m * NCTA + bid], S->redd[0]);
        __syncthreads();
    }
    // final barrier on slot 0 (fused arrive+wait), target = bse[0]+iter+1 (unused so far)
    {
        const unsigned tf = bse[0] + (unsigned)iter + 1u;
        barArrive(0, tf);
        barWait(0, tf);
    }
    if ((sub == 0) && warp < 2) {
        const int m = warp;
        const int base = m * NCTA + pair * 64;
        double cv = __ldcg(&g_costp[base + lane]) + __ldcg(&g_costp[base + lane + 32]);
#pragma unroll
        for (int o = 16; o; o >>= 1)
            cv += __shfl_xor_sync(0xffffffffu, cv, o);
        if (lane == 0)
            gout[pair * 2 + m] = (float)(-(double)EPSV * (double)LN2F * cv);
    }
}

extern "C" void kernel_launch(void* const* d_in, const int* in_sizes, int n_in,
                              void* d_out, int out_size) {
    const float* x  = (const float*)d_in[0];
    const float* y  = (const float*)d_in[1];
    const float* xw = (const float*)d_in[2];
    const float* yw = (const float*)d_in[3];
    float* out = (float*)d_out;
    size_t smem = sizeof(Smem);
    cudaFuncSetAttribute(sinkhorn_kernel, cudaFuncAttributeMaxDynamicSharedMemorySize, (int)smem);
    sinkhorn_kernel<<<NCTA, TPB, smem>>>(x, y, xw, yw, out);
}

// round 11
// speedup vs baseline: 1.1782x; 1.1782x over previous
#include <cuda_runtime.h>

#define NB4    4
#define SUBS   128
#define GRID   512
#define TPB    128
#define PP     1024
#define DD     32
#define RT     8
#define MAXIT  30
#define EPSV   0.1f
#define LN2F   0.69314718055994530942f
#define ALPHA  14.4269504088896340736f   /* 1/(eps*ln2) */
#define THRESH 0.1f

typedef unsigned long long u64;

__device__ float  g_K2[NB4 * PP * PP];        // 16 MB, L2-resident kernel matrix
__device__ float2 g_pm[NB4 * SUBS * PP];      // (max,sum) partials, iter 0
__device__ float  g_ps[NB4 * SUBS * PP];      // plain-sum partials, iter >= 1
__device__ float  g_b2[NB4 * PP];             // B per (batch, col)
__device__ float  g_errpart[GRID];            // per-CTA err partials
__device__ float  g_erriter[NB4];             // published per-batch err (this iter)
__device__ double g_costp[GRID];              // per-CTA cost partials
__device__ unsigned          g_cnt[5 * 32];   // 5 barrier slots (padded)
__device__ volatile unsigned g_gen[5 * 32];

struct Smem {
    float  ystage[256 * DD];   // 32 KB setup staging
    float  bb[PP];             // current B (local copy)
    float  lnu2[PP];
    double redd[TPB];
    float  cmbS[16][9];
    float2 cmbM[16][9];
    float  A2s[RT];
    float  lmu2s[RT];
    float  rowShift[RT];
    float  errw[4];
    float  err4[4];
    float  Sx, Sy;
};

__device__ __forceinline__ float ex2f(float x){ float r; asm("ex2.approx.ftz.f32 %0, %1;" : "=f"(r) : "f"(x)); return r; }
__device__ __forceinline__ float lg2f(float x){ float r; asm("lg2.approx.f32 %0, %1;" : "=f"(r) : "f"(x)); return r; }
__device__ __forceinline__ u64 pk2(float lo, float hi){ u64 r; asm("mov.b64 %0, {%1, %2};" : "=l"(r) : "f"(lo), "f"(hi)); return r; }
__device__ __forceinline__ void upk2(u64 v, float& lo, float& hi){ asm("mov.b64 {%0, %1}, %2;" : "=f"(lo), "=f"(hi) : "l"(v)); }
__device__ __forceinline__ void fma2(u64& d, u64 a, u64 b){ asm("fma.rn.f32x2 %0, %1, %2, %0;" : "+l"(d) : "l"(a), "l"(b)); }
__device__ __forceinline__ u64 add2(u64 a, u64 b){ u64 r; asm("add.rn.f32x2 %0, %1, %2;" : "=l"(r) : "l"(a), "l"(b)); return r; }

// R3-style barrier on slot k with 'count' arrivals.
__device__ __forceinline__ void barx(int k, unsigned target, unsigned count) {
    __syncthreads();
    if (threadIdx.x == 0) {
        __threadfence();
        if (atomicAdd(&g_cnt[k * 32], 1u) == count - 1u) {
            g_cnt[k * 32] = 0;
            __threadfence();
            g_gen[k * 32] = target;
        } else {
            while (g_gen[k * 32] != target) { }
            __threadfence();
        }
    }
    __syncthreads();
}

__global__ void __launch_bounds__(TPB, 4)
sinkhorn_kernel(const float* __restrict__ gx, const float* __restrict__ gy,
                const float* __restrict__ gxw, const float* __restrict__ gyw,
                float* __restrict__ gout)
{
    extern __shared__ __align__(16) char smraw[];
    Smem* S = reinterpret_cast<Smem*>(smraw);

    const int tid  = threadIdx.x;
    const int lane = tid & 31;
    const int warp = tid >> 5;       // 0..3
    const int bid  = blockIdx.x;
    const int nb   = bid >> 7;       // batch 0..3
    const int sub  = bid & 127;      // 0..127
    const int r0   = sub * RT;       // first of 8 owned rows

    unsigned bse[5];
#pragma unroll
    for (int k = 0; k < 5; k++) bse[k] = g_gen[k * 32];

    // ---- global weight sums (redundant per CTA, deterministic) ----
    {
        float px = 0.f, py = 0.f;
        for (int k = tid; k < 4096; k += TPB) { px += gxw[k]; py += gyw[k]; }
        S->redd[tid] = (double)px; __syncthreads();
        for (int s = TPB/2; s > 0; s >>= 1) { if (tid < s) S->redd[tid] += S->redd[tid+s]; __syncthreads(); }
        if (tid == 0) S->Sx = (float)S->redd[0];
        __syncthreads();
        S->redd[tid] = (double)py; __syncthreads();
        for (int s = TPB/2; s > 0; s >>= 1) { if (tid < s) S->redd[tid] += S->redd[tid+s]; __syncthreads(); }
        if (tid == 0) S->Sy = (float)S->redd[0];
        __syncthreads();
    }

    if (tid < RT) {
        S->lmu2s[tid] = lg2f(gxw[nb * PP + r0 + tid] / S->Sx + 1e-8f);
        S->A2s[tid]   = 0.f;
    }
    for (int c = tid; c < PP; c += TPB)
        S->lnu2[c] = lg2f(gyw[nb * PP + c] / S->Sy + 1e-8f);

    // ---- build K2 rows (8 x 1024) into global (L2-resident) ----
    const int kbase = nb * PP * PP;
    const float* ybase = gy + (size_t)nb * PP * DD;
    for (int c = tid; c < PP; c += TPB) {     // temp: ALPHA*|y|^2 in bb
        const float4* yc = (const float4*)(ybase + c * DD);
        float s = 0.f;
#pragma unroll
        for (int q = 0; q < 8; q++) { float4 v = yc[q]; s += v.x*v.x + v.y*v.y + v.z*v.z + v.w*v.w; }
        S->bb[c] = s * ALPHA;
    }
    {
        const int row = lane & 7;
        float xv[32];
        const float4* xr = (const float4*)(gx + (size_t)(nb * PP + r0 + row) * DD);
#pragma unroll
        for (int q = 0; q < 8; q++) {
            float4 v = xr[q];
            xv[4*q] = v.x; xv[4*q+1] = v.y; xv[4*q+2] = v.z; xv[4*q+3] = v.w;
        }
        float x2 = 0.f;
#pragma unroll
        for (int d = 0; d < 32; d++) x2 += xv[d] * xv[d];
        const float cx = ALPHA * x2;
        u64 xp[16];
#pragma unroll
        for (int q = 0; q < 16; q++) xp[q] = pk2(xv[2*q], xv[2*q+1]);
        __syncthreads();

        for (int chunk = 0; chunk < 4; chunk++) {
            const int j0 = chunk * 256;
            const float4* ysrc = (const float4*)(ybase + j0 * DD);
            float4* yst = (float4*)S->ystage;
#pragma unroll
            for (int q = 0; q < 16; q++) yst[tid + TPB * q] = ysrc[tid + TPB * q];
            __syncthreads();
#pragma unroll 4
            for (int step = 0; step < 16; step++) {
                const int jl = step * 16 + warp * 4 + (lane >> 3);
                const ulonglong2* yp = (const ulonglong2*)(S->ystage + jl * DD);
                u64 acc[4] = {0ull, 0ull, 0ull, 0ull};
#pragma unroll
                for (int q = 0; q < 8; q++) {
                    ulonglong2 w = yp[q];
                    fma2(acc[(2*q)   & 3], xp[2*q],     w.x);
                    fma2(acc[(2*q+1) & 3], xp[2*q + 1], w.y);
                }
                u64 st = add2(add2(acc[0], acc[1]), add2(acc[2], acc[3]));
                float lo, hi; upk2(st, lo, hi);
                float dot = lo + hi;
                g_K2[kbase + (r0 + row) * PP + j0 + jl] =
                    fmaf(dot, 2.f * ALPHA, -(cx + S->bb[j0 + jl]));
            }
            __syncthreads();
        }
    }

    // row maxes (iter-0 shift; exact because B=0): warp w handles rows 2w, 2w+1
    {
#pragma unroll
        for (int k = 0; k < 2; k++) {
            const int r = warp * 2 + k;
            const float4* kr = (const float4*)(g_K2 + kbase + (r0 + r) * PP);
            float m = -1e30f;
#pragma unroll
            for (int q = 0; q < 8; q++) {
                float4 a = kr[lane + 32 * q];
                m = fmaxf(m, fmaxf(fmaxf(a.x, a.y), fmaxf(a.z, a.w)));
            }
#pragma unroll
            for (int o = 16; o; o >>= 1) m = fmaxf(m, __shfl_xor_sync(0xffffffffu, m, o));
            if (lane == 0) S->rowShift[r] = m;
        }
    }
#pragma unroll
    for (int cc = 0; cc < 8; cc++) S->bb[tid + TPB * cc] = 0.f;
    __syncthreads();

    const int ct = 4 * tid;                 // owned cols: ct..ct+3, ct+512..ct+515
    const int colL = tid & 7, grp = tid >> 3;

    // ================= Sinkhorn iterations =================
    int iter = 0;
    for (;;) {
        // ---------- row (u) update: warp handles rows 2w, 2w+1 ----------
        {
            const float4* b4  = (const float4*)S->bb;
            const float4* kr0 = (const float4*)(g_K2 + kbase + (r0 + warp * 2 + 0) * PP);
            const float4* kr1 = (const float4*)(g_K2 + kbase + (r0 + warp * 2 + 1) * PP);
            const float m0 = S->rowShift[warp * 2 + 0];
            const float m1 = S->rowShift[warp * 2 + 1];
            float s0 = 0.f, s1 = 0.f;
#pragma unroll
            for (int q = 0; q < 8; q++) {
                const int ix = lane + 32 * q;
                float4 b = b4[ix];
                float4 a0 = kr0[ix], a1 = kr1[ix];
                s0 += ex2f(a0.x + b.x - m0) + ex2f(a0.y + b.y - m0)
                    + ex2f(a0.z + b.z - m0) + ex2f(a0.w + b.w - m0);
                s1 += ex2f(a1.x + b.x - m1) + ex2f(a1.y + b.y - m1)
                    + ex2f(a1.z + b.z - m1) + ex2f(a1.w + b.w - m1);
            }
#pragma unroll
            for (int o = 16; o; o >>= 1) {
                s0 += __shfl_xor_sync(0xffffffffu, s0, o);
                s1 += __shfl_xor_sync(0xffffffffu, s1, o);
            }
            if (lane == 0) {
                float lse0 = m0 + lg2f(s0), lse1 = m1 + lg2f(s1);
                const int r = warp * 2;
                float a0 = S->lmu2s[r+0] - lse0, a1 = S->lmu2s[r+1] - lse1;
                S->errw[warp] = fabsf(a0 - S->A2s[r+0]) + fabsf(a1 - S->A2s[r+1]);
                S->A2s[r+0] = a0; S->A2s[r+1] = a1;
                S->rowShift[r+0] = lse0; S->rowShift[r+1] = lse1;
            }
        }
        __syncthreads();
        if (tid == 0)
            __stcg(&g_errpart[bid],
                   (S->errw[0] + S->errw[1]) + (S->errw[2] + S->errw[3]));

        // ---------- column partials over own 8 rows (8 cols/thread) ----------
        if (iter == 0) {
            float mA[4] = {-1e30f,-1e30f,-1e30f,-1e30f};
            float mB[4] = {-1e30f,-1e30f,-1e30f,-1e30f};
#pragma unroll
            for (int r = 0; r < RT; r++) {
                const float ar = S->A2s[r];
                const float* kr = g_K2 + kbase + (r0 + r) * PP;
                float4 ka = *(const float4*)(kr + ct);
                float4 kb = *(const float4*)(kr + ct + 512);
                mA[0]=fmaxf(mA[0],ka.x+ar); mA[1]=fmaxf(mA[1],ka.y+ar);
                mA[2]=fmaxf(mA[2],ka.z+ar); mA[3]=fmaxf(mA[3],ka.w+ar);
                mB[0]=fmaxf(mB[0],kb.x+ar); mB[1]=fmaxf(mB[1],kb.y+ar);
                mB[2]=fmaxf(mB[2],kb.z+ar); mB[3]=fmaxf(mB[3],kb.w+ar);
            }
            float sA[4] = {0,0,0,0}, sB[4] = {0,0,0,0};
#pragma unroll
            for (int r = 0; r < RT; r++) {
                const float ar = S->A2s[r];
                const float* kr = g_K2 + kbase + (r0 + r) * PP;
                float4 ka = *(const float4*)(kr + ct);
                float4 kb = *(const float4*)(kr + ct + 512);
                sA[0]+=ex2f(ka.x+(ar-mA[0])); sA[1]+=ex2f(ka.y+(ar-mA[1]));
                sA[2]+=ex2f(ka.z+(ar-mA[2])); sA[3]+=ex2f(ka.w+(ar-mA[3]));
                sB[0]+=ex2f(kb.x+(ar-mB[0])); sB[1]+=ex2f(kb.y+(ar-mB[1]));
                sB[2]+=ex2f(kb.z+(ar-mB[2])); sB[3]+=ex2f(kb.w+(ar-mB[3]));
            }
            float2* pm = g_pm + (size_t)bid * PP;
            *(float4*)(pm + ct)       = make_float4(mA[0], sA[0], mA[1], sA[1]);
            *(float4*)(pm + ct + 2)   = make_float4(mA[2], sA[2], mA[3], sA[3]);
            *(float4*)(pm + ct + 512) = make_float4(mB[0], sB[0], mB[1], sB[1]);
            *(float4*)(pm + ct + 514) = make_float4(mB[2], sB[2], mB[3], sB[3]);
        } else {
            float mA[4], mB[4];
#pragma unroll
            for (int j = 0; j < 4; j++) {
                mA[j] = S->lnu2[ct + j]       - S->bb[ct + j];
                mB[j] = S->lnu2[ct + 512 + j] - S->bb[ct + 512 + j];
            }
            float sA[4] = {0,0,0,0}, sB[4] = {0,0,0,0};
#pragma unroll
            for (int r = 0; r < RT; r++) {
                const float ar = S->A2s[r];
                const float* kr = g_K2 + kbase + (r0 + r) * PP;
                float4 ka = *(const float4*)(kr + ct);
                float4 kb = *(const float4*)(kr + ct + 512);
                sA[0]+=ex2f(ka.x+(ar-mA[0])); sA[1]+=ex2f(ka.y+(ar-mA[1]));
                sA[2]+=ex2f(ka.z+(ar-mA[2])); sA[3]+=ex2f(ka.w+(ar-mA[3]));
                sB[0]+=ex2f(kb.x+(ar-mB[0])); sB[1]+=ex2f(kb.y+(ar-mB[1]));
                sB[2]+=ex2f(kb.z+(ar-mB[2])); sB[3]+=ex2f(kb.w+(ar-mB[3]));
            }
            float* ps = g_ps + (size_t)bid * PP;
            *(float4*)(ps + ct)       = make_float4(sA[0], sA[1], sA[2], sA[3]);
            *(float4*)(ps + ct + 512) = make_float4(sB[0], sB[1], sB[2], sB[3]);
        }
        barx(nb, bse[nb] + (unsigned)iter + 1u, SUBS);   // batch-local

        // ---------- combine own 8 columns (tree over 128 subs) ----------
        {
            const int c = sub * 8 + colL;
            if (iter == 0) {
                const float2* base = g_pm + (size_t)(nb * SUBS) * PP + c;
                float2 p = __ldcg(base + (grp * 8 + 0) * PP);
#pragma unroll
                for (int k = 1; k < 8; k++) {
                    float2 q = __ldcg(base + (grp * 8 + k) * PP);
                    float mn = fmaxf(p.x, q.x);
                    p.y = p.y * ex2f(p.x - mn) + q.y * ex2f(q.x - mn);
                    p.x = mn;
                }
                S->cmbM[grp][colL] = p;
                __syncthreads();
                if (tid < 8) {
                    float2 p2 = S->cmbM[0][tid];
#pragma unroll
                    for (int g = 1; g < 16; g++) {
                        float2 q = S->cmbM[g][tid];
                        float mn = fmaxf(p2.x, q.x);
                        p2.y = p2.y * ex2f(p2.x - mn) + q.y * ex2f(q.x - mn);
                        p2.x = mn;
                    }
                    const int cc = sub * 8 + tid;
                    float lse = p2.x + lg2f(p2.y);
                    __stcg(&g_b2[nb * PP + cc], S->lnu2[cc] - lse);
                }
            } else {
                const float* base = g_ps + (size_t)(nb * SUBS) * PP + c;
                float s = 0.f;
#pragma unroll
                for (int k = 0; k < 8; k++) s += __ldcg(base + (grp * 8 + k) * PP);
                S->cmbS[grp][colL] = s;
                __syncthreads();
                if (tid < 8) {
                    float tot = 0.f;
#pragma unroll
                    for (int g = 0; g < 16; g++) tot += S->cmbS[g][tid];
                    const int cc = sub * 8 + tid;
                    float shift = S->lnu2[cc] - S->bb[cc];
                    float lse = shift + lg2f(tot);
                    __stcg(&g_b2[nb * PP + cc], S->lnu2[cc] - lse);
                }
            }
        }
        // publisher: batch err (fixed-order, deterministic)
        if (sub == 0 && warp == 0) {
            float e = __ldcg(&g_errpart[nb * SUBS + lane])
                    + __ldcg(&g_errpart[nb * SUBS + lane + 32])
                    + __ldcg(&g_errpart[nb * SUBS + lane + 64])
                    + __ldcg(&g_errpart[nb * SUBS + lane + 96]);
#pragma unroll
            for (int o = 16; o; o >>= 1) e += __shfl_xor_sync(0xffffffffu, e, o);
            if (lane == 0) __stcg(&g_erriter[nb], e);
        }
        barx(4, bse[4] + (unsigned)iter + 1u, GRID);     // global

        // ---------- reload B; decide ----------
        {
            const float4* gb4 = (const float4*)(g_b2 + nb * PP);
            ((float4*)S->bb)[tid]       = __ldcg(gb4 + tid);
            ((float4*)S->bb)[tid + 128] = __ldcg(gb4 + tid + 128);
        }
        if (tid < 4) S->err4[tid] = __ldcg(&g_erriter[tid]);
        __syncthreads();
        float ev = (S->err4[0] + S->err4[1]) + (S->err4[2] + S->err4[3]);

        iter++;
        if (iter >= MAXIT) break;
        if (ev * (EPSV * LN2F * 0.25f) < THRESH) break;
    }

    // ---- final cost: cost_n = -eps*ln2 * sum 2^(K2+A+B) * K2 ----
    {
        float bcA[4], bcB[4];
#pragma unroll
        for (int j = 0; j < 4; j++) {
            bcA[j] = S->bb[ct + j];
            bcB[j] = S->bb[ct + 512 + j];
        }
        float acc = 0.f;
#pragma unroll
        for (int r = 0; r < RT; r++) {
            const float ar = S->A2s[r];
            const float* kr = g_K2 + kbase + (r0 + r) * PP;
            float4 ka = *(const float4*)(kr + ct);
            float4 kb = *(const float4*)(kr + ct + 512);
            acc = fmaf(ex2f(ka.x + ar + bcA[0]), ka.x, acc);
            acc = fmaf(ex2f(ka.y + ar + bcA[1]), ka.y, acc);
            acc = fmaf(ex2f(ka.z + ar + bcA[2]), ka.z, acc);
            acc = fmaf(ex2f(ka.w + ar + bcA[3]), ka.w, acc);
            acc = fmaf(ex2f(kb.x + ar + bcB[0]), kb.x, acc);
            acc = fmaf(ex2f(kb.y + ar + bcB[1]), kb.y, acc);
            acc = fmaf(ex2f(kb.z + ar + bcB[2]), kb.z, acc);
            acc = fmaf(ex2f(kb.w + ar + bcB[3]), kb.w, acc);
        }
        S->redd[tid] = (double)acc; __syncthreads();
        for (int s = TPB/2; s > 0; s >>= 1) { if (tid < s) S->redd[tid] += S->redd[tid+s]; __syncthreads(); }
        if (tid == 0) __stcg(&g_costp[bid], S->redd[0]);
    }
    barx(4, bse[4] + (unsigned)iter + 1u, GRID);
    if (sub == 0 && warp == 0) {
        double cv = __ldcg(&g_costp[nb * SUBS + lane])
                  + __ldcg(&g_costp[nb * SUBS + lane + 32])
                  + __ldcg(&g_costp[nb * SUBS + lane + 64])
                  + __ldcg(&g_costp[nb * SUBS + lane + 96]);
#pragma unroll
        for (int o = 16; o; o >>= 1)
            cv += __shfl_xor_sync(0xffffffffu, cv, o);
        if (lane == 0)
            gout[nb] = (float)(-(double)EPSV * (double)LN2F * cv);
    }
}

extern "C" void kernel_launch(void* const* d_in, const int* in_sizes, int n_in,
                              void* d_out, int out_size) {
    const float* x  = (const float*)d_in[0];
    const float* y  = (const float*)d_in[1];
    const float* xw = (const float*)d_in[2];
    const float* yw = (const float*)d_in[3];
    float* out = (float*)d_out;
    size_t smem = sizeof(Smem);
    cudaFuncSetAttribute(sinkhorn_kernel, cudaFuncAttributeMaxDynamicSharedMemorySize, (int)smem);
    sinkhorn_kernel<<<GRID, TPB, smem>>>(x, y, xw, yw, out);
}

// round 12
// speedup vs baseline: 1.9957x; 1.6939x over previous
#include <cuda_runtime.h>

#define NCTA   128
#define TPB    256
#define PP     1024
#define DD     32
#define RS     1032
#define MAXIT  30
#define EPSV   0.1f
#define LN2F   0.69314718055994530942f
#define ALPHA  14.4269504088896340736f   /* 1/(eps*ln2) */
#define THRESH 0.1f

typedef unsigned long long u64;

__device__ unsigned          g_cnt = 0;
__device__ volatile unsigned g_gen = 0;
__device__ float2 g_pm[NCTA * PP];                 // iter-0 (max,sum) partials
__device__ float  g_csum[(MAXIT + 1) * 4 * PP];    // per-iter per-batch col sums (atomic)
__device__ float  g_errb[(MAXIT + 1) * 4 * 8];     // per-iter per-batch err (padded)
__device__ float  g_b2[4 * PP];                    // B after iter 0
__device__ double g_costp[NCTA];

struct Smem {
    float  K2[32 * RS];        // 132096 B
    float  bb[PP];             // current B (local)
    float  lnu2[PP];
    float  ystage[256 * DD];   // 32 KB setup staging
    double redd[TPB];
    float2 cmb[8][32];         // iter-0 combine tree
    float  A2s[32];
    float  lmu2s[32];
    float  rowShift[32];
    float  errw[8];
    float  err4[4];
    float  Sx, Sy;
};

__device__ __forceinline__ float ex2f(float x){ float r; asm("ex2.approx.ftz.f32 %0, %1;" : "=f"(r) : "f"(x)); return r; }
__device__ __forceinline__ float lg2f(float x){ float r; asm("lg2.approx.f32 %0, %1;" : "=f"(r) : "f"(x)); return r; }
__device__ __forceinline__ u64 pk2(float lo, float hi){ u64 r; asm("mov.b64 %0, {%1, %2};" : "=l"(r) : "f"(lo), "f"(hi)); return r; }
__device__ __forceinline__ void upk2(u64 v, float& lo, float& hi){ asm("mov.b64 {%0, %1}, %2;" : "=f"(lo), "=f"(hi) : "l"(v)); }
__device__ __forceinline__ void fma2(u64& d, u64 a, u64 b){ asm("fma.rn.f32x2 %0, %1, %2, %0;" : "+l"(d) : "l"(a), "l"(b)); }
__device__ __forceinline__ u64 add2(u64 a, u64 b){ u64 r; asm("add.rn.f32x2 %0, %1, %2;" : "=l"(r) : "l"(a), "l"(b)); return r; }

// R3-style global barrier: single atomic counter + single generation flag.
__device__ __forceinline__ void gbar(unsigned target) {
    __syncthreads();
    if (threadIdx.x == 0) {
        __threadfence();
        if (atomicAdd(&g_cnt, 1u) == NCTA - 1u) {
            g_cnt = 0;
            __threadfence();
            g_gen = target;
        } else {
            while (g_gen != target) { }
            __threadfence();
        }
    }
    __syncthreads();
}

__global__ void __launch_bounds__(TPB, 1)
sinkhorn_kernel(const float* __restrict__ gx, const float* __restrict__ gy,
                const float* __restrict__ gxw, const float* __restrict__ gyw,
                float* __restrict__ gout)
{
    extern __shared__ __align__(16) char smraw[];
    Smem* S = reinterpret_cast<Smem*>(smraw);

    const int tid  = threadIdx.x;
    const int lane = tid & 31;
    const int warp = tid >> 5;       // 0..7
    const int bid  = blockIdx.x;
    const int nb   = bid >> 5;
    const int sub  = bid & 31;
    const int r0   = sub * 32;

    unsigned tgt = g_gen;    // quiescent base; read before any release

    // ---- zero per-launch atomic accumulators (disjoint slices) ----
    for (int k = bid * TPB + tid; k < (MAXIT + 1) * 4 * PP; k += NCTA * TPB)
        g_csum[k] = 0.f;
    if (bid == 0)
        for (int k = tid; k < (MAXIT + 1) * 4 * 8; k += TPB) g_errb[k] = 0.f;

    // ---- global weight sums (redundant per CTA, deterministic) ----
    {
        float px = 0.f, py = 0.f;
        for (int k = tid; k < 4096; k += TPB) { px += gxw[k]; py += gyw[k]; }
        S->redd[tid] = (double)px; __syncthreads();
        for (int s = TPB/2; s > 0; s >>= 1) { if (tid < s) S->redd[tid] += S->redd[tid+s]; __syncthreads(); }
        if (tid == 0) S->Sx = (float)S->redd[0];
        __syncthreads();
        S->redd[tid] = (double)py; __syncthreads();
        for (int s = TPB/2; s > 0; s >>= 1) { if (tid < s) S->redd[tid] += S->redd[tid+s]; __syncthreads(); }
        if (tid == 0) S->Sy = (float)S->redd[0];
        __syncthreads();
    }

    if (tid < 32) {
        S->lmu2s[tid] = lg2f(gxw[nb * PP + r0 + tid] / S->Sx + 1e-8f);
        S->A2s[tid]   = 0.f;
    }
    for (int c = tid; c < PP; c += TPB)
        S->lnu2[c] = lg2f(gyw[nb * PP + c] / S->Sy + 1e-8f);

    // ---- build K2 = -C/(eps*ln2) in SMEM ----
    const float* ybase = gy + (size_t)nb * PP * DD;
    for (int c = tid; c < PP; c += TPB) {
        const float4* yc = (const float4*)(ybase + c * DD);
        float s = 0.f;
#pragma unroll
        for (int q = 0; q < 8; q++) { float4 v = yc[q]; s += v.x*v.x + v.y*v.y + v.z*v.z + v.w*v.w; }
        S->bb[c] = s * ALPHA;   // temp: ALPHA*|y|^2
    }
    float xv[32];
    {
        const float4* xr = (const float4*)(gx + (size_t)(nb * PP + r0 + lane) * DD);
#pragma unroll
        for (int q = 0; q < 8; q++) {
            float4 v = xr[q];
            xv[4*q] = v.x; xv[4*q+1] = v.y; xv[4*q+2] = v.z; xv[4*q+3] = v.w;
        }
    }
    float x2 = 0.f;
#pragma unroll
    for (int d = 0; d < 32; d++) x2 += xv[d] * xv[d];
    const float cx = ALPHA * x2;
    u64 xp[16];
#pragma unroll
    for (int q = 0; q < 16; q++) xp[q] = pk2(xv[2*q], xv[2*q+1]);
    __syncthreads();

    for (int chunk = 0; chunk < 4; chunk++) {
        const int j0 = chunk * 256;
        const float4* ysrc = (const float4*)(ybase + j0 * DD);
        float4* yst = (float4*)S->ystage;
#pragma unroll
        for (int q = 0; q < 8; q++) yst[tid + 256 * q] = ysrc[tid + 256 * q];
        __syncthreads();
#pragma unroll 4
        for (int m = 0; m < 32; m++) {
            const int jj = warp + 8 * m;
            const ulonglong2* yp = (const ulonglong2*)(S->ystage + jj * DD);
            u64 acc[4] = {0ull, 0ull, 0ull, 0ull};
#pragma unroll
            for (int q = 0; q < 8; q++) {
                ulonglong2 w = yp[q];
                fma2(acc[(2*q)   & 3], xp[2*q],     w.x);
                fma2(acc[(2*q+1) & 3], xp[2*q + 1], w.y);
            }
            u64 st = add2(add2(acc[0], acc[1]), add2(acc[2], acc[3]));
            float lo, hi; upk2(st, lo, hi);
            float dot = lo + hi;
            S->K2[lane * RS + j0 + jj] = fmaf(dot, 2.f * ALPHA, -(cx + S->bb[j0 + jj]));
        }
        __syncthreads();
    }

    // row maxes (iter-0 shift; exact since B=0 at iter 0)
#pragma unroll
    for (int k = 0; k < 4; k++) {
        const int r = warp * 4 + k;
        const float4* kr = (const float4*)(S->K2 + r * RS);
        float m = -1e30f;
#pragma unroll
        for (int q = 0; q < 8; q++) {
            float4 a = kr[lane + 32 * q];
            m = fmaxf(m, fmaxf(fmaxf(a.x, a.y), fmaxf(a.z, a.w)));
        }
#pragma unroll
        for (int o = 16; o; o >>= 1) m = fmaxf(m, __shfl_xor_sync(0xffffffffu, m, o));
        if (lane == 0) S->rowShift[r] = m;
    }
#pragma unroll
    for (int cc = 0; cc < 4; cc++) S->bb[tid + 256 * cc] = 0.f;

    gbar(++tgt);   // accumulator zeroing visible before any atomicAdd

    const int c0 = 2 * tid, c1 = 2 * tid + 1, c2 = 2 * tid + 512, c3 = 2 * tid + 513;

    // ================= Sinkhorn iterations =================
    int iter = 0;
    for (;;) {
        // ---------- row (u) update: shift = prev row LSE; 4 rows share bb loads ----------
        {
            const float4* b4 = (const float4*)S->bb;
            const float4* kr0 = (const float4*)(S->K2 + (warp * 4 + 0) * RS);
            const float4* kr1 = (const float4*)(S->K2 + (warp * 4 + 1) * RS);
            const float4* kr2 = (const float4*)(S->K2 + (warp * 4 + 2) * RS);
            const float4* kr3 = (const float4*)(S->K2 + (warp * 4 + 3) * RS);
            const float m0 = S->rowShift[warp * 4 + 0];
            const float m1 = S->rowShift[warp * 4 + 1];
            const float m2 = S->rowShift[warp * 4 + 2];
            const float m3 = S->rowShift[warp * 4 + 3];
            float s0 = 0.f, s1 = 0.f, s2 = 0.f, s3 = 0.f;
#pragma unroll
            for (int q = 0; q < 8; q++) {
                const int ix = lane + 32 * q;
                float4 b = b4[ix];
                float4 a0 = kr0[ix], a1 = kr1[ix], a2 = kr2[ix], a3 = kr3[ix];
                s0 += ex2f(a0.x + b.x - m0) + ex2f(a0.y + b.y - m0) + ex2f(a0.z + b.z - m0) + ex2f(a0.w + b.w - m0);
                s1 += ex2f(a1.x + b.x - m1) + ex2f(a1.y + b.y - m1) + ex2f(a1.z + b.z - m1) + ex2f(a1.w + b.w - m1);
                s2 += ex2f(a2.x + b.x - m2) + ex2f(a2.y + b.y - m2) + ex2f(a2.z + b.z - m2) + ex2f(a2.w + b.w - m2);
                s3 += ex2f(a3.x + b.x - m3) + ex2f(a3.y + b.y - m3) + ex2f(a3.z + b.z - m3) + ex2f(a3.w + b.w - m3);
            }
#pragma unroll
            for (int o = 16; o; o >>= 1) {
                s0 += __shfl_xor_sync(0xffffffffu, s0, o);
                s1 += __shfl_xor_sync(0xffffffffu, s1, o);
                s2 += __shfl_xor_sync(0xffffffffu, s2, o);
                s3 += __shfl_xor_sync(0xffffffffu, s3, o);
            }
            if (lane == 0) {
                float lse0 = m0 + lg2f(s0), lse1 = m1 + lg2f(s1);
                float lse2 = m2 + lg2f(s2), lse3 = m3 + lg2f(s3);
                const int r = warp * 4;
                float a0 = S->lmu2s[r+0] - lse0, a1 = S->lmu2s[r+1] - lse1;
                float a2 = S->lmu2s[r+2] - lse2, a3 = S->lmu2s[r+3] - lse3;
                S->errw[warp] = fabsf(a0 - S->A2s[r+0]) + fabsf(a1 - S->A2s[r+1])
                              + fabsf(a2 - S->A2s[r+2]) + fabsf(a3 - S->A2s[r+3]);
                S->A2s[r+0] = a0; S->A2s[r+1] = a1; S->A2s[r+2] = a2; S->A2s[r+3] = a3;
                S->rowShift[r+0] = lse0; S->rowShift[r+1] = lse1;
                S->rowShift[r+2] = lse2; S->rowShift[r+3] = lse3;
            }
        }
        __syncthreads();
        if (tid == 0) {
            float e = ((S->errw[0] + S->errw[1]) + (S->errw[2] + S->errw[3]))
                    + ((S->errw[4] + S->errw[5]) + (S->errw[6] + S->errw[7]));
            atomicAdd(&g_errb[(iter * 4 + nb) * 8], e);
        }

        // ---------- column reduction ----------
        if (iter == 0) {
            // (max,sum) partials + tree combine (runs once)
            float m0=-1e30f, m1=-1e30f, m2=-1e30f, m3=-1e30f;
#pragma unroll
            for (int r = 0; r < 32; r++) {
                const float ar = S->A2s[r];
                const float* kr = S->K2 + r * RS;
                float2 ka = *(const float2*)(kr + c0);
                float2 kb = *(const float2*)(kr + c2);
                m0 = fmaxf(m0, ka.x + ar); m1 = fmaxf(m1, ka.y + ar);
                m2 = fmaxf(m2, kb.x + ar); m3 = fmaxf(m3, kb.y + ar);
            }
            float s0=0.f, s1=0.f, s2=0.f, s3=0.f;
#pragma unroll
            for (int r = 0; r < 32; r++) {
                const float ar = S->A2s[r];
                const float* kr = S->K2 + r * RS;
                float2 ka = *(const float2*)(kr + c0);
                float2 kb = *(const float2*)(kr + c2);
                s0 += ex2f(ka.x + (ar - m0)); s1 += ex2f(ka.y + (ar - m1));
                s2 += ex2f(kb.x + (ar - m2)); s3 += ex2f(kb.y + (ar - m3));
            }
            float2* pm = g_pm + (size_t)bid * PP;
            *(float4*)(pm + c0) = make_float4(m0, s0, m1, s1);
            *(float4*)(pm + c2) = make_float4(m2, s2, m3, s3);
            gbar(++tgt);

            // tree combine own 32 columns -> B -> g_b2
            {
                const float2* cpb = g_pm + (size_t)(nb * 32) * PP + (sub * 32 + lane);
                float2 p = __ldcg(cpb + warp * PP);
#pragma unroll
                for (int k = 1; k < 4; k++) {
                    float2 q = __ldcg(cpb + (warp + 8 * k) * PP);
                    float mn = fmaxf(p.x, q.x);
                    p.y = p.y * ex2f(p.x - mn) + q.y * ex2f(q.x - mn);
                    p.x = mn;
                }
                S->cmb[warp][lane] = p;
            }
            __syncthreads();
            if (warp == 0) {
                float2 p = S->cmb[0][lane];
#pragma unroll
                for (int w = 1; w < 8; w++) {
                    float2 q = S->cmb[w][lane];
                    float mn = fmaxf(p.x, q.x);
                    p.y = p.y * ex2f(p.x - mn) + q.y * ex2f(q.x - mn);
                    p.x = mn;
                }
                float B = S->lnu2[sub * 32 + lane] - (p.x + lg2f(p.y));
                __stcg(&g_b2[nb * PP + sub * 32 + lane], B);
            }
            gbar(++tgt);
            ((float4*)S->bb)[tid] = __ldcg(((const float4*)(g_b2 + nb * PP)) + tid);
        } else {
            // plain sums with shift = lnu - B_old, accumulated via L2 atomics
            const float mc0 = S->lnu2[c0] - S->bb[c0];
            const float mc1 = S->lnu2[c1] - S->bb[c1];
            const float mc2 = S->lnu2[c2] - S->bb[c2];
            const float mc3 = S->lnu2[c3] - S->bb[c3];
            float s0 = 0.f, s1 = 0.f, s2 = 0.f, s3 = 0.f;
#pragma unroll
            for (int r = 0; r < 32; r++) {
                const float ar = S->A2s[r];
                const float* kr = S->K2 + r * RS;
                float2 ka = *(const float2*)(kr + c0);
                float2 kb = *(const float2*)(kr + c2);
                s0 += ex2f(ka.x + (ar - mc0));
                s1 += ex2f(ka.y + (ar - mc1));
                s2 += ex2f(kb.x + (ar - mc2));
                s3 += ex2f(kb.y + (ar - mc3));
            }
            float* cs = g_csum + (size_t)(iter * 4 + nb) * PP;
            atomicAdd(cs + c0, s0);
            atomicAdd(cs + c1, s1);
            atomicAdd(cs + c2, s2);
            atomicAdd(cs + c3, s3);
            gbar(++tgt);

            // local B update: B_new = B_old - log2(colsum)
            const int c4 = 4 * tid;
            float4 sv = __ldcg((const float4*)(g_csum + (size_t)(iter * 4 + nb) * PP + c4));
            float4 bo = *(float4*)(S->bb + c4);
            bo.x -= lg2f(sv.x); bo.y -= lg2f(sv.y);
            bo.z -= lg2f(sv.z); bo.w -= lg2f(sv.w);
            *(float4*)(S->bb + c4) = bo;
        }

        // ---------- err gather + decide ----------
        if (tid < 4) S->err4[tid] = __ldcg(&g_errb[(iter * 4 + tid) * 8]);
        __syncthreads();
        float ev = (S->err4[0] + S->err4[1]) + (S->err4[2] + S->err4[3]);

        iter++;
        if (iter >= MAXIT) break;
        if (ev * (EPSV * LN2F * 0.25f) < THRESH) break;
    }

    // ---- final cost: cost_n = -eps*ln2 * sum 2^(K2+A+B) * K2 ----
    {
        const float bc0 = S->bb[c0], bc1 = S->bb[c1];
        const float bc2 = S->bb[c2], bc3 = S->bb[c3];
        float acc = 0.f;
#pragma unroll 8
        for (int r = 0; r < 32; r++) {
            const float ar = S->A2s[r];
            const float* kr = S->K2 + r * RS;
            float2 ka = *(const float2*)(kr + c0);
            float2 kb = *(const float2*)(kr + c2);
            acc = fmaf(ex2f(ka.x + ar + bc0), ka.x, acc);
            acc = fmaf(ex2f(ka.y + ar + bc1), ka.y, acc);
            acc = fmaf(ex2f(kb.x + ar + bc2), kb.x, acc);
            acc = fmaf(ex2f(kb.y + ar + bc3), kb.y, acc);
        }
        S->redd[tid] = (double)acc; __syncthreads();
        for (int s = TPB/2; s > 0; s >>= 1) { if (tid < s) S->redd[tid] += S->redd[tid+s]; __syncthreads(); }
        if (tid == 0) __stcg(&g_costp[bid], S->redd[0]);
    }
    gbar(++tgt);
    if (sub == 0 && warp == 0) {
        double cv = __ldcg(&g_costp[nb * 32 + lane]);
#pragma unroll
        for (int o = 16; o; o >>= 1)
            cv += __shfl_xor_sync(0xffffffffu, cv, o);
        if (lane == 0)
            gout[nb] = (float)(-(double)EPSV * (double)LN2F * cv);
    }
}

extern "C" void kernel_launch(void* const* d_in, const int* in_sizes, int n_in,
                              void* d_out, int out_size) {
    const float* x  = (const float*)d_in[0];
    const float* y  = (const float*)d_in[1];
    const float* xw = (const float*)d_in[2];
    const float* yw = (const float*)d_in[3];
    float* out = (float*)d_out;
    size_t smem = sizeof(Smem);
    cudaFuncSetAttribute(sinkhorn_kernel, cudaFuncAttributeMaxDynamicSharedMemorySize, (int)smem);
    sinkhorn_kernel<<<NCTA, TPB, smem>>>(x, y, xw, yw, out);
}